// round 1
// baseline (speedup 1.0000x reference)
#include <cuda_runtime.h>
#include <math.h>

#define Bb   2
#define Nn   1024
#define DIMM 1024
#define Hh   8
#define DHh  64
#define DIi  512
#define BN   (Bb*Nn)

static __device__ __constant__ float EPSf = 1.1920929e-07f;

// ---------------- scratch (device globals, no runtime alloc) ----------------
__device__ float g_xa[BN*DIMM];
__device__ float g_qi[BN*DIMM];
__device__ float g_ki[BN*DIMM];
__device__ float g_vi[BN*DIMM];
__device__ float g_qp[BN*DIi];
__device__ float g_kp[BN*DIi];
__device__ float g_vp[BN*DIi];
__device__ float g_y [BN*DIi];
__device__ float g_lr[BN*Hh];
__device__ float g_de[BN*Hh];
__device__ float g_mo[BN*Hh];

// ---------------- 1. RMSNorm over DIM ----------------
__global__ void k_rmsnorm(const float* __restrict__ x, const float* __restrict__ w) {
    int row = blockIdx.x;
    int tid = threadIdx.x;                       // 256 threads, 1 float4 each
    const float4* xr = (const float4*)(x + (size_t)row * DIMM);
    float4 xv = xr[tid];
    float ss = xv.x*xv.x + xv.y*xv.y + xv.z*xv.z + xv.w*xv.w;
    #pragma unroll
    for (int o = 16; o > 0; o >>= 1) ss += __shfl_xor_sync(0xffffffffu, ss, o);
    __shared__ float sred[8];
    if ((tid & 31) == 0) sred[tid >> 5] = ss;
    __syncthreads();
    float tot = 0.f;
    #pragma unroll
    for (int i = 0; i < 8; i++) tot += sred[i];
    float inv = rsqrtf(tot * (1.0f / DIMM) + EPSf);
    float4 wv = ((const float4*)w)[tid];
    float4 o;
    o.x = xv.x * inv * wv.x; o.y = xv.y * inv * wv.y;
    o.z = xv.z * inv * wv.z; o.w = xv.w * inv * wv.w;
    ((float4*)g_xa)[(size_t)row * (DIMM/4) + tid] = o;
}

// ---------------- 2. fused 3x depthwise conv (K=4, pad 2, keep first N) ----
__global__ void k_conv(const float* __restrict__ cq, const float* __restrict__ ck,
                       const float* __restrict__ cv) {
    int row = blockIdx.x;
    int b = row / Nn, t = row - b * Nn;
    int d4 = threadIdx.x;                        // float4 index, d = 4*d4
    int d  = d4 * 4;
    float xr[4][4];
    #pragma unroll
    for (int jj = 0; jj < 4; jj++) {
        int tt = t - 2 + jj;
        float4 v = make_float4(0.f, 0.f, 0.f, 0.f);
        if (tt >= 0 && tt < Nn)
            v = ((const float4*)g_xa)[((size_t)(b*Nn + tt)) * (DIMM/4) + d4];
        xr[jj][0] = v.x; xr[jj][1] = v.y; xr[jj][2] = v.z; xr[jj][3] = v.w;
    }
    const float* cws[3] = {cq, ck, cv};
    float* outs[3] = {g_qi, g_ki, g_vi};
    #pragma unroll
    for (int cI = 0; cI < 3; cI++) {
        float oo[4];
        #pragma unroll
        for (int e = 0; e < 4; e++) {
            float4 wv = ((const float4*)cws[cI])[d + e];   // conv_w[d+e][0..3]
            oo[e] = xr[0][e]*wv.x + xr[1][e]*wv.y + xr[2][e]*wv.z + xr[3][e]*wv.w;
        }
        float4 o = make_float4(oo[0], oo[1], oo[2], oo[3]);
        ((float4*)outs[cI])[(size_t)row * (DIMM/4) + d4] = o;
    }
}

// ---------------- 3. tiled FP32 GEMM: C[M,N] = A[M,K]@B[K,N] -------------
// 64x64 tile, K-tile 32, 256 threads, 4x4 microtile. All dims % 64/32 == 0.
__global__ void k_gemm(const float* __restrict__ A, const float* __restrict__ Bm,
                       float* __restrict__ C, int M, int Nc, int Kc) {
    __shared__ float As[32][65];   // transposed A tile, padded: conflict-free
    __shared__ float Bs[32][64];
    int tid = threadIdx.x;
    int tx = tid & 15, ty = tid >> 4;
    int row0 = blockIdx.y * 64, col0 = blockIdx.x * 64;
    float acc[4][4] = {};
    for (int k0 = 0; k0 < Kc; k0 += 32) {
        #pragma unroll
        for (int p = 0; p < 2; p++) {
            int ar = (tid >> 3) + p * 32;
            int ac = (tid & 7) * 4;
            float4 v = *(const float4*)(A + (size_t)(row0 + ar) * Kc + k0 + ac);
            As[ac+0][ar] = v.x; As[ac+1][ar] = v.y;
            As[ac+2][ar] = v.z; As[ac+3][ar] = v.w;
        }
        #pragma unroll
        for (int p = 0; p < 2; p++) {
            int br = (tid >> 4) + p * 16;
            int bc = (tid & 15) * 4;
            *(float4*)&Bs[br][bc] = *(const float4*)(Bm + (size_t)(k0 + br) * Nc + col0 + bc);
        }
        __syncthreads();
        #pragma unroll
        for (int kk = 0; kk < 32; kk++) {
            float a0 = As[kk][ty*4+0], a1 = As[kk][ty*4+1];
            float a2 = As[kk][ty*4+2], a3 = As[kk][ty*4+3];
            float4 b = *(const float4*)&Bs[kk][tx*4];
            acc[0][0] += a0*b.x; acc[0][1] += a0*b.y; acc[0][2] += a0*b.z; acc[0][3] += a0*b.w;
            acc[1][0] += a1*b.x; acc[1][1] += a1*b.y; acc[1][2] += a1*b.z; acc[1][3] += a1*b.w;
            acc[2][0] += a2*b.x; acc[2][1] += a2*b.y; acc[2][2] += a2*b.z; acc[2][3] += a2*b.w;
            acc[3][0] += a3*b.x; acc[3][1] += a3*b.y; acc[3][2] += a3*b.z; acc[3][3] += a3*b.w;
        }
        __syncthreads();
    }
    #pragma unroll
    for (int i = 0; i < 4; i++) {
        float4 o = make_float4(acc[i][0], acc[i][1], acc[i][2], acc[i][3]);
        *(float4*)(C + (size_t)(row0 + ty*4 + i) * Nc + col0 + tx*4) = o;
    }
}

// ---------------- 4. sigmoid gate projections ----------------
__global__ void k_gates(const float* __restrict__ lw, const float* __restrict__ lb,
                        const float* __restrict__ dw, const float* __restrict__ db,
                        const float* __restrict__ mw, const float* __restrict__ mb) {
    int row = blockIdx.x;
    int w = threadIdx.x >> 5, l = threadIdx.x & 31;
    const float* xa = g_xa + (size_t)row * DIMM;
    for (int idx = w; idx < 24; idx += 8) {
        int gi = idx >> 3, h = idx & 7;
        const float* W = (gi == 0) ? lw : ((gi == 1) ? dw : mw);
        float s = 0.f;
        for (int d = l; d < DIMM; d += 32) s += xa[d] * W[d * Hh + h];
        #pragma unroll
        for (int o = 16; o > 0; o >>= 1) s += __shfl_xor_sync(0xffffffffu, s, o);
        if (l == 0) {
            const float* bb = (gi == 0) ? lb : ((gi == 1) ? db : mb);
            float v = 1.f / (1.f + expf(-(s + bb[h])));
            float* out = (gi == 0) ? g_lr : ((gi == 1) ? g_de : g_mo);
            out[row * Hh + h] = v;
        }
    }
}

// ---------------- 5. per-head RMSNorm of q, k (in place) ----------------
__global__ void k_mhnorm(const float* __restrict__ gq, const float* __restrict__ gk) {
    int row = blockIdx.x;                     // b*N + t
    int h = threadIdx.x >> 5, l = threadIdx.x & 31;
    size_t off = (size_t)row * DIi + h * DHh;
    {
        float a0 = g_qp[off + l], a1 = g_qp[off + l + 32];
        float ss = a0*a0 + a1*a1;
        #pragma unroll
        for (int o = 16; o > 0; o >>= 1) ss += __shfl_xor_sync(0xffffffffu, ss, o);
        float rms = sqrtf(ss) * 0.125f;       // * DH^{-1/2}
        float inv = 1.f / fmaxf(rms, 1e-8f);
        g_qp[off + l]      = a0 * inv * gq[h*DHh + l];
        g_qp[off + l + 32] = a1 * inv * gq[h*DHh + l + 32];
    }
    {
        float a0 = g_kp[off + l], a1 = g_kp[off + l + 32];
        float ss = a0*a0 + a1*a1;
        #pragma unroll
        for (int o = 16; o > 0; o >>= 1) ss += __shfl_xor_sync(0xffffffffu, ss, o);
        float rms = sqrtf(ss) * 0.125f;
        float inv = 1.f / fmaxf(rms, 1e-8f);
        g_kp[off + l]      = a0 * inv * gk[h*DHh + l];
        g_kp[off + l + 32] = a1 * inv * gk[h*DHh + l + 32];
    }
}

// ---------------- 6. sequential double scan, 1 block per (b,h) ------------
// Z_t = mom*Z + (-v k^T);  S_t = decay*S - lr*Z_t;  y_t = S_{t-1} q_t
__global__ void k_scan() {
    int b = blockIdx.x / Hh, h = blockIdx.x % Hh;
    int tid = threadIdx.x;            // 256
    int r = tid >> 2;                 // row 0..63  (v dim)
    int c = tid & 3;                  // col group
    int j0 = c * 16;                  // cols j0..j0+15 (k dim)
    __shared__ float sq[64], sk[64], sv[64], sg[3];
    float Z[16], S[16];
    #pragma unroll
    for (int j = 0; j < 16; j++) { Z[j] = 0.f; S[j] = 0.f; }
    const size_t base = (size_t)b * Nn * DIi + h * DHh;
    for (int t = 0; t < Nn; t++) {
        __syncthreads();
        if (tid < 64) {
            size_t off = base + (size_t)t * DIi + tid;
            sq[tid] = g_qp[off]; sk[tid] = g_kp[off]; sv[tid] = g_vp[off];
        } else if (tid < 67) {
            const float* gp = (tid == 64) ? g_lr : ((tid == 65) ? g_de : g_mo);
            sg[tid - 64] = gp[(b*Nn + t) * Hh + h];
        }
        __syncthreads();
        // y_t = S_{t-1} q_t
        float p = 0.f;
        #pragma unroll
        for (int jj = 0; jj < 16; jj++) p += S[jj] * sq[j0 + jj];
        p += __shfl_xor_sync(0xffffffffu, p, 1);
        p += __shfl_xor_sync(0xffffffffu, p, 2);
        if (c == 0) g_y[base + (size_t)t * DIi + r] = p;
        float vr = sv[r], lrt = sg[0], det = sg[1], mot = sg[2];
        #pragma unroll
        for (int jj = 0; jj < 16; jj++) {
            Z[jj] = mot * Z[jj] - vr * sk[j0 + jj];
            S[jj] = det * S[jj] - lrt * Z[jj];
        }
    }
}

// ---------------- launch ----------------
extern "C" void kernel_launch(void* const* d_in, const int* in_sizes, int n_in,
                              void* d_out, int out_size) {
    const float* x      = (const float*)d_in[0];
    const float* w_rms  = (const float*)d_in[1];
    const float* wq     = (const float*)d_in[2];
    const float* wk     = (const float*)d_in[3];
    const float* wv     = (const float*)d_in[4];
    const float* wo     = (const float*)d_in[5];
    const float* conv_q = (const float*)d_in[6];
    const float* conv_k = (const float*)d_in[7];
    const float* conv_v = (const float*)d_in[8];
    const float* gamma_q= (const float*)d_in[9];
    const float* gamma_k= (const float*)d_in[10];
    const float* lr_w   = (const float*)d_in[11];
    const float* lr_b   = (const float*)d_in[12];
    const float* decay_w= (const float*)d_in[13];
    const float* decay_b= (const float*)d_in[14];
    const float* mom_w  = (const float*)d_in[15];
    const float* mom_b  = (const float*)d_in[16];
    float* out = (float*)d_out;

    float *p_qi, *p_ki, *p_vi, *p_qp, *p_kp, *p_vp, *p_y;
    cudaGetSymbolAddress((void**)&p_qi, g_qi);
    cudaGetSymbolAddress((void**)&p_ki, g_ki);
    cudaGetSymbolAddress((void**)&p_vi, g_vi);
    cudaGetSymbolAddress((void**)&p_qp, g_qp);
    cudaGetSymbolAddress((void**)&p_kp, g_kp);
    cudaGetSymbolAddress((void**)&p_vp, g_vp);
    cudaGetSymbolAddress((void**)&p_y,  g_y);

    k_rmsnorm<<<BN, 256>>>(x, w_rms);
    k_conv<<<BN, 256>>>(conv_q, conv_k, conv_v);
    dim3 gqkv(DIi/64, BN/64);
    k_gemm<<<gqkv, 256>>>(p_qi, wq, p_qp, BN, DIi, DIMM);
    k_gemm<<<gqkv, 256>>>(p_ki, wk, p_kp, BN, DIi, DIMM);
    k_gemm<<<gqkv, 256>>>(p_vi, wv, p_vp, BN, DIi, DIMM);
    k_gates<<<BN, 256>>>(lr_w, lr_b, decay_w, decay_b, mom_w, mom_b);
    k_mhnorm<<<BN, 256>>>(gamma_q, gamma_k);
    k_scan<<<Bb*Hh, 256>>>();
    dim3 gout(DIMM/64, BN/64);
    k_gemm<<<gout, 256>>>(p_y, wo, out, BN, DIMM, DIi);
}

// round 2
// speedup vs baseline: 1.6222x; 1.6222x over previous
#include <cuda_runtime.h>
#include <math.h>

#define Bb   2
#define Nn   1024
#define DIMM 1024
#define Hh   8
#define DHh  64
#define DIi  512
#define BN   (Bb*Nn)
#define T4   4

static __device__ __constant__ float EPSf = 1.1920929e-07f;

// ---------------- scratch ----------------
__device__ float g_xa[BN*DIMM];
__device__ float g_qi[BN*DIMM];
__device__ float g_ki[BN*DIMM];
__device__ float g_vi[BN*DIMM];
__device__ float g_qp[BN*DIi];
__device__ float g_kp[BN*DIi];
__device__ float g_vp[BN*DIi];
__device__ float g_y [BN*DIi];
__device__ float g_lr[BN*Hh];
__device__ float g_de[BN*Hh];
__device__ float g_mo[BN*Hh];

// ---------------- 1. RMSNorm ----------------
__global__ void k_rmsnorm(const float* __restrict__ x, const float* __restrict__ w) {
    int row = blockIdx.x;
    int tid = threadIdx.x;
    const float4* xr = (const float4*)(x + (size_t)row * DIMM);
    float4 xv = xr[tid];
    float ss = xv.x*xv.x + xv.y*xv.y + xv.z*xv.z + xv.w*xv.w;
    #pragma unroll
    for (int o = 16; o > 0; o >>= 1) ss += __shfl_xor_sync(0xffffffffu, ss, o);
    __shared__ float sred[8];
    if ((tid & 31) == 0) sred[tid >> 5] = ss;
    __syncthreads();
    float tot = 0.f;
    #pragma unroll
    for (int i = 0; i < 8; i++) tot += sred[i];
    float inv = rsqrtf(tot * (1.0f / DIMM) + EPSf);
    float4 wv = ((const float4*)w)[tid];
    float4 o;
    o.x = xv.x * inv * wv.x; o.y = xv.y * inv * wv.y;
    o.z = xv.z * inv * wv.z; o.w = xv.w * inv * wv.w;
    ((float4*)g_xa)[(size_t)row * (DIMM/4) + tid] = o;
}

// ---------------- 2. fused 3x depthwise conv ----------------
__global__ void k_conv(const float* __restrict__ cq, const float* __restrict__ ck,
                       const float* __restrict__ cv) {
    int row = blockIdx.x;
    int b = row / Nn, t = row - b * Nn;
    int d4 = threadIdx.x;
    int d  = d4 * 4;
    float xr[4][4];
    #pragma unroll
    for (int jj = 0; jj < 4; jj++) {
        int tt = t - 2 + jj;
        float4 v = make_float4(0.f, 0.f, 0.f, 0.f);
        if (tt >= 0 && tt < Nn)
            v = ((const float4*)g_xa)[((size_t)(b*Nn + tt)) * (DIMM/4) + d4];
        xr[jj][0] = v.x; xr[jj][1] = v.y; xr[jj][2] = v.z; xr[jj][3] = v.w;
    }
    const float* cws[3] = {cq, ck, cv};
    float* outs[3] = {g_qi, g_ki, g_vi};
    #pragma unroll
    for (int cI = 0; cI < 3; cI++) {
        float oo[4];
        #pragma unroll
        for (int e = 0; e < 4; e++) {
            float4 wv = ((const float4*)cws[cI])[d + e];
            oo[e] = xr[0][e]*wv.x + xr[1][e]*wv.y + xr[2][e]*wv.z + xr[3][e]*wv.w;
        }
        ((float4*)outs[cI])[(size_t)row * (DIMM/4) + d4] =
            make_float4(oo[0], oo[1], oo[2], oo[3]);
    }
}

// ---------------- 3. GEMM body: 128x64 tile, 8x4 microtile, KT=16 ----------
__device__ __forceinline__ void gemm128_body(const float* __restrict__ A,
                                             const float* __restrict__ Bm,
                                             float* __restrict__ C,
                                             int Nc, int Kc) {
    __shared__ float As[16][132];   // transposed A tile (k-major), padded
    __shared__ float Bs[16][64];
    int tid = threadIdx.x;
    int tx = tid & 15, ty = tid >> 4;
    int row0 = blockIdx.y * 128, col0 = blockIdx.x * 64;
    float acc[8][4] = {};
    for (int k0 = 0; k0 < Kc; k0 += 16) {
        #pragma unroll
        for (int p = 0; p < 2; p++) {
            int lid = tid * 2 + p;            // 0..511
            int m = lid >> 2, kc = (lid & 3) * 4;
            float4 v = *(const float4*)(A + (size_t)(row0 + m) * Kc + k0 + kc);
            As[kc+0][m] = v.x; As[kc+1][m] = v.y;
            As[kc+2][m] = v.z; As[kc+3][m] = v.w;
        }
        {
            int br = tid >> 4, bc = (tid & 15) * 4;
            *(float4*)&Bs[br][bc] = *(const float4*)(Bm + (size_t)(k0 + br) * Nc + col0 + bc);
        }
        __syncthreads();
        #pragma unroll
        for (int kk = 0; kk < 16; kk++) {
            float ar[8];
            *(float4*)&ar[0] = *(const float4*)&As[kk][ty*8];
            *(float4*)&ar[4] = *(const float4*)&As[kk][ty*8+4];
            float4 b = *(const float4*)&Bs[kk][tx*4];
            #pragma unroll
            for (int i = 0; i < 8; i++) {
                acc[i][0] += ar[i]*b.x; acc[i][1] += ar[i]*b.y;
                acc[i][2] += ar[i]*b.z; acc[i][3] += ar[i]*b.w;
            }
        }
        __syncthreads();
    }
    #pragma unroll
    for (int i = 0; i < 8; i++) {
        *(float4*)(C + (size_t)(row0 + ty*8 + i) * Nc + col0 + tx*4) =
            make_float4(acc[i][0], acc[i][1], acc[i][2], acc[i][3]);
    }
}

// fused QKV: blockIdx.z selects which GEMM
__global__ void k_gemm3(const float* __restrict__ A0, const float* __restrict__ A1,
                        const float* __restrict__ A2, const float* __restrict__ B0,
                        const float* __restrict__ B1, const float* __restrict__ B2,
                        float* __restrict__ C0, float* __restrict__ C1,
                        float* __restrict__ C2, int Nc, int Kc) {
    const float* A = (blockIdx.z == 0) ? A0 : ((blockIdx.z == 1) ? A1 : A2);
    const float* Bm = (blockIdx.z == 0) ? B0 : ((blockIdx.z == 1) ? B1 : B2);
    float* C = (blockIdx.z == 0) ? C0 : ((blockIdx.z == 1) ? C1 : C2);
    gemm128_body(A, Bm, C, Nc, Kc);
}

__global__ void k_gemm1(const float* __restrict__ A, const float* __restrict__ Bm,
                        float* __restrict__ C, int Nc, int Kc) {
    gemm128_body(A, Bm, C, Nc, Kc);
}

// ---------------- 4. sigmoid gate projections ----------------
__global__ void k_gates(const float* __restrict__ lw, const float* __restrict__ lb,
                        const float* __restrict__ dw, const float* __restrict__ db,
                        const float* __restrict__ mw, const float* __restrict__ mb) {
    int row = blockIdx.x;
    int w = threadIdx.x >> 5, l = threadIdx.x & 31;
    const float* xa = g_xa + (size_t)row * DIMM;
    for (int idx = w; idx < 24; idx += 8) {
        int gi = idx >> 3, h = idx & 7;
        const float* W = (gi == 0) ? lw : ((gi == 1) ? dw : mw);
        float s = 0.f;
        for (int d = l; d < DIMM; d += 32) s += xa[d] * W[d * Hh + h];
        #pragma unroll
        for (int o = 16; o > 0; o >>= 1) s += __shfl_xor_sync(0xffffffffu, s, o);
        if (l == 0) {
            const float* bb = (gi == 0) ? lb : ((gi == 1) ? db : mb);
            float v = 1.f / (1.f + expf(-(s + bb[h])));
            float* out = (gi == 0) ? g_lr : ((gi == 1) ? g_de : g_mo);
            out[row * Hh + h] = v;
        }
    }
}

// ---------------- 5. per-head RMSNorm of q, k ----------------
__global__ void k_mhnorm(const float* __restrict__ gq, const float* __restrict__ gk) {
    int row = blockIdx.x;
    int h = threadIdx.x >> 5, l = threadIdx.x & 31;
    size_t off = (size_t)row * DIi + h * DHh;
    {
        float a0 = g_qp[off + l], a1 = g_qp[off + l + 32];
        float ss = a0*a0 + a1*a1;
        #pragma unroll
        for (int o = 16; o > 0; o >>= 1) ss += __shfl_xor_sync(0xffffffffu, ss, o);
        float inv = 1.f / fmaxf(sqrtf(ss) * 0.125f, 1e-8f);
        g_qp[off + l]      = a0 * inv * gq[h*DHh + l];
        g_qp[off + l + 32] = a1 * inv * gq[h*DHh + l + 32];
    }
    {
        float a0 = g_kp[off + l], a1 = g_kp[off + l + 32];
        float ss = a0*a0 + a1*a1;
        #pragma unroll
        for (int o = 16; o > 0; o >>= 1) ss += __shfl_xor_sync(0xffffffffu, ss, o);
        float inv = 1.f / fmaxf(sqrtf(ss) * 0.125f, 1e-8f);
        g_kp[off + l]      = a0 * inv * gk[h*DHh + l];
        g_kp[off + l + 32] = a1 * inv * gk[h*DHh + l + 32];
    }
}

// ---------------- 6. scan: 4-step groups, double-buffered prefetch --------
__global__ void k_scan() {
    int b = blockIdx.x >> 3, h = blockIdx.x & 7;
    int tid = threadIdx.x;            // 256
    int r = tid >> 2, c = tid & 3, j0 = c * 16;
    __shared__ float sq[2][T4][64], sk[2][T4][64], sv[2][T4][64], sg[2][T4][4];
    float Z[16], S[16];
    #pragma unroll
    for (int j = 0; j < 16; j++) { Z[j] = 0.f; S[j] = 0.f; }
    const size_t base = (size_t)b * Nn * DIi + h * DHh;

    // loader roles
    int la = tid >> 6;                 // 0,1,2 -> q,k,v ; 3 -> gates
    int lrem = tid & 63;
    int lstep = lrem >> 4, lf4 = lrem & 15;
    const float* srcp = (la == 0) ? g_qp : ((la == 1) ? g_kp : g_vp);
    int gstep = lrem / 3, ggi = lrem - gstep * 3;   // valid when lrem < 12
    const float* gsrc = (ggi == 0) ? g_lr : ((ggi == 1) ? g_de : g_mo);

    float4 pf = make_float4(0.f,0.f,0.f,0.f);
    float pg = 0.f;
    // load group 0 into buffer 0
    if (la < 3)
        pf = *(const float4*)(srcp + base + (size_t)lstep * DIi + lf4 * 4);
    else if (lrem < 12)
        pg = gsrc[(b*Nn + gstep) * Hh + h];
    if (la == 0)      *(float4*)&sq[0][lstep][lf4*4] = pf;
    else if (la == 1) *(float4*)&sk[0][lstep][lf4*4] = pf;
    else if (la == 2) *(float4*)&sv[0][lstep][lf4*4] = pf;
    else if (lrem < 12) sg[0][gstep][ggi] = pg;
    __syncthreads();

    int cur = 0;
    for (int g0 = 0; g0 < Nn / T4; g0++) {
        int t0 = g0 * T4;
        bool hasnext = (g0 + 1 < Nn / T4);
        if (hasnext) {
            int tn = t0 + T4;
            if (la < 3)
                pf = *(const float4*)(srcp + base + (size_t)(tn + lstep) * DIi + lf4 * 4);
            else if (lrem < 12)
                pg = gsrc[(b*Nn + tn + gstep) * Hh + h];
        }
        #pragma unroll
        for (int s = 0; s < T4; s++) {
            float p = 0.f;
            #pragma unroll
            for (int jj = 0; jj < 16; jj++) p += S[jj] * sq[cur][s][j0 + jj];
            p += __shfl_xor_sync(0xffffffffu, p, 1);
            p += __shfl_xor_sync(0xffffffffu, p, 2);
            if (c == 0) g_y[base + (size_t)(t0 + s) * DIi + r] = p;
            float vr  = sv[cur][s][r];
            float lrt = sg[cur][s][0], det = sg[cur][s][1], mot = sg[cur][s][2];
            #pragma unroll
            for (int jj = 0; jj < 16; jj++) {
                Z[jj] = mot * Z[jj] - vr * sk[cur][s][j0 + jj];
                S[jj] = det * S[jj] - lrt * Z[jj];
            }
        }
        __syncthreads();
        if (hasnext) {
            int nxt = cur ^ 1;
            if (la == 0)      *(float4*)&sq[nxt][lstep][lf4*4] = pf;
            else if (la == 1) *(float4*)&sk[nxt][lstep][lf4*4] = pf;
            else if (la == 2) *(float4*)&sv[nxt][lstep][lf4*4] = pf;
            else if (lrem < 12) sg[nxt][gstep][ggi] = pg;
        }
        __syncthreads();
        cur ^= 1;
    }
}

// ---------------- launch ----------------
extern "C" void kernel_launch(void* const* d_in, const int* in_sizes, int n_in,
                              void* d_out, int out_size) {
    const float* x      = (const float*)d_in[0];
    const float* w_rms  = (const float*)d_in[1];
    const float* wq     = (const float*)d_in[2];
    const float* wk     = (const float*)d_in[3];
    const float* wv     = (const float*)d_in[4];
    const float* wo     = (const float*)d_in[5];
    const float* conv_q = (const float*)d_in[6];
    const float* conv_k = (const float*)d_in[7];
    const float* conv_v = (const float*)d_in[8];
    const float* gamma_q= (const float*)d_in[9];
    const float* gamma_k= (const float*)d_in[10];
    const float* lr_w   = (const float*)d_in[11];
    const float* lr_b   = (const float*)d_in[12];
    const float* decay_w= (const float*)d_in[13];
    const float* decay_b= (const float*)d_in[14];
    const float* mom_w  = (const float*)d_in[15];
    const float* mom_b  = (const float*)d_in[16];
    float* out = (float*)d_out;

    float *p_qi, *p_ki, *p_vi, *p_qp, *p_kp, *p_vp, *p_y;
    cudaGetSymbolAddress((void**)&p_qi, g_qi);
    cudaGetSymbolAddress((void**)&p_ki, g_ki);
    cudaGetSymbolAddress((void**)&p_vi, g_vi);
    cudaGetSymbolAddress((void**)&p_qp, g_qp);
    cudaGetSymbolAddress((void**)&p_kp, g_kp);
    cudaGetSymbolAddress((void**)&p_vp, g_vp);
    cudaGetSymbolAddress((void**)&p_y,  g_y);

    k_rmsnorm<<<BN, 256>>>(x, w_rms);
    k_conv<<<BN, 256>>>(conv_q, conv_k, conv_v);
    dim3 gqkv(DIi/64, BN/128, 3);
    k_gemm3<<<gqkv, 256>>>(p_qi, p_ki, p_vi, wq, wk, wv, p_qp, p_kp, p_vp, DIi, DIMM);
    k_gates<<<BN, 256>>>(lr_w, lr_b, decay_w, decay_b, mom_w, mom_b);
    k_mhnorm<<<BN, 256>>>(gamma_q, gamma_k);
    k_scan<<<Bb*Hh, 256>>>();
    dim3 gout(DIMM/64, BN/128);
    k_gemm1<<<gout, 256>>>(p_y, wo, out, DIMM, DIi);
}

// round 3
// speedup vs baseline: 2.6832x; 1.6540x over previous
#include <cuda_runtime.h>
#include <math.h>

#define Bb   2
#define Nn   1024
#define DIMM 1024
#define Hh   8
#define DHh  64
#define DIi  512
#define BN   (Bb*Nn)
#define TG   8
#define JB   8

static __device__ __constant__ float EPSf = 1.1920929e-07f;
typedef unsigned long long u64;

// ---------------- scratch ----------------
__device__ float g_xa[BN*DIMM];
__device__ float g_qi[BN*DIMM];
__device__ float g_ki[BN*DIMM];
__device__ float g_vi[BN*DIMM];
__device__ float g_qp[BN*DIi];
__device__ float g_kp[BN*DIi];
__device__ float g_vp[BN*DIi];
__device__ float g_y [BN*DIi];
__device__ float g_ga[BN*24];

// ---------------- f32x2 helpers ----------------
__device__ __forceinline__ u64 pack2(float lo, float hi) {
    u64 r; asm("mov.b64 %0, {%1, %2};" : "=l"(r) : "f"(lo), "f"(hi)); return r;
}
__device__ __forceinline__ void fma2(u64& d, u64 a, u64 b) {
    asm("fma.rn.f32x2 %0, %1, %2, %3;" : "=l"(d) : "l"(a), "l"(b), "l"(d));
}
__device__ __forceinline__ void unpack2(u64 v, float& lo, float& hi) {
    asm("mov.b64 {%0, %1}, %2;" : "=f"(lo), "=f"(hi) : "l"(v));
}

// ---------------- 1. RMSNorm ----------------
__global__ void k_rmsnorm(const float* __restrict__ x, const float* __restrict__ w) {
    int row = blockIdx.x;
    int tid = threadIdx.x;
    const float4* xr = (const float4*)(x + (size_t)row * DIMM);
    float4 xv = xr[tid];
    float ss = xv.x*xv.x + xv.y*xv.y + xv.z*xv.z + xv.w*xv.w;
    #pragma unroll
    for (int o = 16; o > 0; o >>= 1) ss += __shfl_xor_sync(0xffffffffu, ss, o);
    __shared__ float sred[8];
    if ((tid & 31) == 0) sred[tid >> 5] = ss;
    __syncthreads();
    float tot = 0.f;
    #pragma unroll
    for (int i = 0; i < 8; i++) tot += sred[i];
    float inv = rsqrtf(tot * (1.0f / DIMM) + EPSf);
    float4 wv = ((const float4*)w)[tid];
    float4 o;
    o.x = xv.x * inv * wv.x; o.y = xv.y * inv * wv.y;
    o.z = xv.z * inv * wv.z; o.w = xv.w * inv * wv.w;
    ((float4*)g_xa)[(size_t)row * (DIMM/4) + tid] = o;
}

// ---------------- 2. fused 3x depthwise conv ----------------
__global__ void k_conv(const float* __restrict__ cq, const float* __restrict__ ck,
                       const float* __restrict__ cv) {
    int row = blockIdx.x;
    int b = row / Nn, t = row - b * Nn;
    int d4 = threadIdx.x;
    int d  = d4 * 4;
    float xr[4][4];
    #pragma unroll
    for (int jj = 0; jj < 4; jj++) {
        int tt = t - 2 + jj;
        float4 v = make_float4(0.f, 0.f, 0.f, 0.f);
        if (tt >= 0 && tt < Nn)
            v = ((const float4*)g_xa)[((size_t)(b*Nn + tt)) * (DIMM/4) + d4];
        xr[jj][0] = v.x; xr[jj][1] = v.y; xr[jj][2] = v.z; xr[jj][3] = v.w;
    }
    const float* cws[3] = {cq, ck, cv};
    float* outs[3] = {g_qi, g_ki, g_vi};
    #pragma unroll
    for (int cI = 0; cI < 3; cI++) {
        float oo[4];
        #pragma unroll
        for (int e = 0; e < 4; e++) {
            float4 wv = ((const float4*)cws[cI])[d + e];
            oo[e] = xr[0][e]*wv.x + xr[1][e]*wv.y + xr[2][e]*wv.z + xr[3][e]*wv.w;
        }
        ((float4*)outs[cI])[(size_t)row * (DIMM/4) + d4] =
            make_float4(oo[0], oo[1], oo[2], oo[3]);
    }
}

// ---------------- 3. GEMM: 128x128 tile, f32x2, reg double-buffer ----------
__device__ __forceinline__ void gemm_body(const float* __restrict__ A,
                                          const float* __restrict__ Bm,
                                          float* __restrict__ C,
                                          int Nc, int Kc) {
    __shared__ float As[16][132];   // k-major transposed A tile
    __shared__ float Bs[16][128];
    int tid = threadIdx.x;
    int tx = tid & 15, ty = tid >> 4;
    int row0 = blockIdx.y * 128, col0 = blockIdx.x * 128;
    u64 acc[4][8];
    #pragma unroll
    for (int i = 0; i < 4; i++)
        #pragma unroll
        for (int j = 0; j < 8; j++) acc[i][j] = 0ull;

    int am0 = (tid*2)   >> 2, ak0 = ((tid*2)   & 3) * 4;
    int am1 = (tid*2+1) >> 2, ak1 = ((tid*2+1) & 3) * 4;
    int br0 = tid >> 5,        bc0 = (tid & 31) * 4;
    int br1 = (tid+256) >> 5,  bc1 = bc0;

    float4 ra0, ra1, rb0, rb1;
    ra0 = *(const float4*)(A + (size_t)(row0 + am0) * Kc + ak0);
    ra1 = *(const float4*)(A + (size_t)(row0 + am1) * Kc + ak1);
    rb0 = *(const float4*)(Bm + (size_t)br0 * Nc + col0 + bc0);
    rb1 = *(const float4*)(Bm + (size_t)br1 * Nc + col0 + bc1);

    for (int k0 = 0; k0 < Kc; k0 += 16) {
        As[ak0+0][am0]=ra0.x; As[ak0+1][am0]=ra0.y; As[ak0+2][am0]=ra0.z; As[ak0+3][am0]=ra0.w;
        As[ak1+0][am1]=ra1.x; As[ak1+1][am1]=ra1.y; As[ak1+2][am1]=ra1.z; As[ak1+3][am1]=ra1.w;
        *(float4*)&Bs[br0][bc0] = rb0;
        *(float4*)&Bs[br1][bc1] = rb1;
        __syncthreads();
        if (k0 + 16 < Kc) {
            int kn = k0 + 16;
            ra0 = *(const float4*)(A + (size_t)(row0 + am0) * Kc + kn + ak0);
            ra1 = *(const float4*)(A + (size_t)(row0 + am1) * Kc + kn + ak1);
            rb0 = *(const float4*)(Bm + (size_t)(kn + br0) * Nc + col0 + bc0);
            rb1 = *(const float4*)(Bm + (size_t)(kn + br1) * Nc + col0 + bc1);
        }
        #pragma unroll
        for (int kk = 0; kk < 16; kk++) {
            float4 aL = *(const float4*)&As[kk][ty*4];
            float4 aH = *(const float4*)&As[kk][64 + ty*4];
            float4 bL = *(const float4*)&Bs[kk][tx*4];
            float4 bH = *(const float4*)&Bs[kk][64 + tx*4];
            u64 ap[4] = { pack2(aL.x,aL.y), pack2(aL.z,aL.w),
                          pack2(aH.x,aH.y), pack2(aH.z,aH.w) };
            u64 bp[8] = { pack2(bL.x,bL.x), pack2(bL.y,bL.y), pack2(bL.z,bL.z), pack2(bL.w,bL.w),
                          pack2(bH.x,bH.x), pack2(bH.y,bH.y), pack2(bH.z,bH.z), pack2(bH.w,bH.w) };
            #pragma unroll
            for (int rp = 0; rp < 4; rp++)
                #pragma unroll
                for (int j = 0; j < 8; j++) fma2(acc[rp][j], ap[rp], bp[j]);
        }
        __syncthreads();
    }
    #pragma unroll
    for (int rp = 0; rp < 4; rp++) {
        int rbase = (rp < 2) ? (ty*4 + rp*2) : (64 + ty*4 + (rp-2)*2);
        float lo[8], hi[8];
        #pragma unroll
        for (int j = 0; j < 8; j++) unpack2(acc[rp][j], lo[j], hi[j]);
        *(float4*)(C + (size_t)(row0+rbase)*Nc + col0 + tx*4)      = make_float4(lo[0],lo[1],lo[2],lo[3]);
        *(float4*)(C + (size_t)(row0+rbase)*Nc + col0 + 64 + tx*4) = make_float4(lo[4],lo[5],lo[6],lo[7]);
        *(float4*)(C + (size_t)(row0+rbase+1)*Nc + col0 + tx*4)      = make_float4(hi[0],hi[1],hi[2],hi[3]);
        *(float4*)(C + (size_t)(row0+rbase+1)*Nc + col0 + 64 + tx*4) = make_float4(hi[4],hi[5],hi[6],hi[7]);
    }
}

__global__ __launch_bounds__(256, 1)
void k_gemm3(const float* __restrict__ A0, const float* __restrict__ A1,
             const float* __restrict__ A2, const float* __restrict__ B0,
             const float* __restrict__ B1, const float* __restrict__ B2,
             float* __restrict__ C0, float* __restrict__ C1,
             float* __restrict__ C2, int Nc, int Kc) {
    const float* A = (blockIdx.z == 0) ? A0 : ((blockIdx.z == 1) ? A1 : A2);
    const float* Bm = (blockIdx.z == 0) ? B0 : ((blockIdx.z == 1) ? B1 : B2);
    float* C = (blockIdx.z == 0) ? C0 : ((blockIdx.z == 1) ? C1 : C2);
    gemm_body(A, Bm, C, Nc, Kc);
}

__global__ __launch_bounds__(256, 1)
void k_gemm1(const float* __restrict__ A, const float* __restrict__ Bm,
             float* __restrict__ C, int Nc, int Kc) {
    gemm_body(A, Bm, C, Nc, Kc);
}

// ---------------- 4. gate projections as split-K GEMM (raw accum) ---------
__global__ void k_gates2(const float* __restrict__ lw, const float* __restrict__ dw,
                         const float* __restrict__ mw) {
    __shared__ float As[16][132];
    __shared__ float Ws[16][24];
    int tid = threadIdx.x;
    int hh = tid & 7, ty = tid >> 3;          // ty 0..31 -> 4 rows each
    int row0 = blockIdx.x * 128;
    int kbase = blockIdx.y * 128;
    float acc[4][3] = {};
    for (int k0 = kbase; k0 < kbase + 128; k0 += 16) {
        #pragma unroll
        for (int p = 0; p < 2; p++) {
            int lid = tid + p * 256;
            int m = lid >> 2, kc = (lid & 3) * 4;
            float4 v = *(const float4*)(g_xa + (size_t)(row0+m)*DIMM + k0 + kc);
            As[kc+0][m]=v.x; As[kc+1][m]=v.y; As[kc+2][m]=v.z; As[kc+3][m]=v.w;
        }
        if (tid < 128) {
            int kk = tid >> 3, h2 = tid & 7;
            Ws[kk][h2]      = lw[(k0+kk)*Hh + h2];
            Ws[kk][8+h2]    = dw[(k0+kk)*Hh + h2];
            Ws[kk][16+h2]   = mw[(k0+kk)*Hh + h2];
        }
        __syncthreads();
        #pragma unroll
        for (int kk = 0; kk < 16; kk++) {
            float4 a = *(const float4*)&As[kk][ty*4];
            float w0 = Ws[kk][hh], w1 = Ws[kk][8+hh], w2 = Ws[kk][16+hh];
            acc[0][0] += a.x*w0; acc[0][1] += a.x*w1; acc[0][2] += a.x*w2;
            acc[1][0] += a.y*w0; acc[1][1] += a.y*w1; acc[1][2] += a.y*w2;
            acc[2][0] += a.z*w0; acc[2][1] += a.z*w1; acc[2][2] += a.z*w2;
            acc[3][0] += a.w*w0; acc[3][1] += a.w*w1; acc[3][2] += a.w*w2;
        }
        __syncthreads();
    }
    #pragma unroll
    for (int i = 0; i < 4; i++) {
        int row = row0 + ty*4 + i;
        atomicAdd(&g_ga[row*24 + hh],      acc[i][0]);
        atomicAdd(&g_ga[row*24 + 8 + hh],  acc[i][1]);
        atomicAdd(&g_ga[row*24 + 16 + hh], acc[i][2]);
    }
}

// ---------------- 5. per-head RMSNorm of q, k ----------------
__global__ void k_mhnorm(const float* __restrict__ gq, const float* __restrict__ gk) {
    int row = blockIdx.x;
    int h = threadIdx.x >> 5, l = threadIdx.x & 31;
    size_t off = (size_t)row * DIi + h * DHh;
    {
        float a0 = g_qp[off + l], a1 = g_qp[off + l + 32];
        float ss = a0*a0 + a1*a1;
        #pragma unroll
        for (int o = 16; o > 0; o >>= 1) ss += __shfl_xor_sync(0xffffffffu, ss, o);
        float inv = 1.f / fmaxf(sqrtf(ss) * 0.125f, 1e-8f);
        g_qp[off + l]      = a0 * inv * gq[h*DHh + l];
        g_qp[off + l + 32] = a1 * inv * gq[h*DHh + l + 32];
    }
    {
        float a0 = g_kp[off + l], a1 = g_kp[off + l + 32];
        float ss = a0*a0 + a1*a1;
        #pragma unroll
        for (int o = 16; o > 0; o >>= 1) ss += __shfl_xor_sync(0xffffffffu, ss, o);
        float inv = 1.f / fmaxf(sqrtf(ss) * 0.125f, 1e-8f);
        g_kp[off + l]      = a0 * inv * gk[h*DHh + l];
        g_kp[off + l + 32] = a1 * inv * gk[h*DHh + l + 32];
    }
}

// ---------------- 6. scan: 8 col-blocks per (b,h), 8-step groups ----------
__global__ void k_scan(const float* __restrict__ lb, const float* __restrict__ db,
                       const float* __restrict__ mb) {
    int bh = blockIdx.x >> 3, jb = blockIdx.x & 7;
    int b = bh >> 3, h = bh & 7;
    int j0g = jb * JB;
    int tid = threadIdx.x;           // 256
    int r = tid >> 2, c = tid & 3;   // row, col-pair group (2 cols each)
    __shared__ float sq[2][TG][JB], sk[2][TG][JB], sv[2][TG][64], sg[2][TG][4];
    float Z0=0.f, Z1=0.f, S0=0.f, S1=0.f;
    const size_t base = (size_t)b * Nn * DIi + h * DHh;

    // loader roles
    int vstep = tid >> 6, vrow = tid & 63;            // + second load at vstep+4
    bool qrole = (tid < 64), krole = (tid >= 64 && tid < 128);
    bool grole = (tid >= 128 && tid < 152);
    int qkstep = (tid & 63) >> 3, qkj = tid & 7;
    int gidx = tid - 128;
    int gstep = gidx / 3, ggi = gidx - gstep * 3;
    float gbias = 0.f;
    if (grole) {
        const float* bsrc = (ggi == 0) ? lb : ((ggi == 1) ? db : mb);
        gbias = bsrc[h];
    }

    float pv0, pv1, pq = 0.f, pk = 0.f, pg = 0.f;
    pv0 = g_vp[base + (size_t)vstep * DIi + vrow];
    pv1 = g_vp[base + (size_t)(vstep+4) * DIi + vrow];
    if (qrole) pq = g_qp[base + (size_t)qkstep * DIi + j0g + qkj];
    if (krole) pk = g_kp[base + (size_t)qkstep * DIi + j0g + qkj];
    if (grole) {
        float raw = g_ga[(size_t)(b*Nn + gstep)*24 + ggi*8 + h] + gbias;
        pg = 1.f / (1.f + __expf(-raw));
    }
    sv[0][vstep][vrow] = pv0;
    sv[0][vstep+4][vrow] = pv1;
    if (qrole) sq[0][qkstep][qkj] = pq;
    if (krole) sk[0][qkstep][qkj] = pk;
    if (grole) sg[0][gstep][ggi] = pg;
    __syncthreads();

    int cur = 0;
    for (int g0 = 0; g0 < Nn / TG; g0++) {
        int t0 = g0 * TG;
        bool hasnext = (g0 + 1 < Nn / TG);
        if (hasnext) {
            int tn = t0 + TG;
            pv0 = g_vp[base + (size_t)(tn+vstep) * DIi + vrow];
            pv1 = g_vp[base + (size_t)(tn+vstep+4) * DIi + vrow];
            if (qrole) pq = g_qp[base + (size_t)(tn+qkstep) * DIi + j0g + qkj];
            if (krole) pk = g_kp[base + (size_t)(tn+qkstep) * DIi + j0g + qkj];
            if (grole) {
                float raw = g_ga[(size_t)(b*Nn + tn + gstep)*24 + ggi*8 + h] + gbias;
                pg = 1.f / (1.f + __expf(-raw));
            }
        }
        #pragma unroll
        for (int s = 0; s < TG; s++) {
            float q0 = sq[cur][s][c*2], q1 = sq[cur][s][c*2+1];
            float p = S0*q0 + S1*q1;
            p += __shfl_xor_sync(0xffffffffu, p, 1);
            p += __shfl_xor_sync(0xffffffffu, p, 2);
            if (c == 0) atomicAdd(&g_y[base + (size_t)(t0+s)*DIi + r], p);
            float vr  = sv[cur][s][r];
            float k0v = sk[cur][s][c*2], k1v = sk[cur][s][c*2+1];
            float lrt = sg[cur][s][0], det = sg[cur][s][1], mot = sg[cur][s][2];
            Z0 = mot*Z0 - vr*k0v;  S0 = det*S0 - lrt*Z0;
            Z1 = mot*Z1 - vr*k1v;  S1 = det*S1 - lrt*Z1;
        }
        __syncthreads();
        if (hasnext) {
            int nxt = cur ^ 1;
            sv[nxt][vstep][vrow] = pv0;
            sv[nxt][vstep+4][vrow] = pv1;
            if (qrole) sq[nxt][qkstep][qkj] = pq;
            if (krole) sk[nxt][qkstep][qkj] = pk;
            if (grole) sg[nxt][gstep][ggi] = pg;
        }
        __syncthreads();
        cur ^= 1;
    }
}

// ---------------- launch ----------------
extern "C" void kernel_launch(void* const* d_in, const int* in_sizes, int n_in,
                              void* d_out, int out_size) {
    const float* x      = (const float*)d_in[0];
    const float* w_rms  = (const float*)d_in[1];
    const float* wq     = (const float*)d_in[2];
    const float* wk     = (const float*)d_in[3];
    const float* wv     = (const float*)d_in[4];
    const float* wo     = (const float*)d_in[5];
    const float* conv_q = (const float*)d_in[6];
    const float* conv_k = (const float*)d_in[7];
    const float* conv_v = (const float*)d_in[8];
    const float* gamma_q= (const float*)d_in[9];
    const float* gamma_k= (const float*)d_in[10];
    const float* lr_w   = (const float*)d_in[11];
    const float* lr_b   = (const float*)d_in[12];
    const float* decay_w= (const float*)d_in[13];
    const float* decay_b= (const float*)d_in[14];
    const float* mom_w  = (const float*)d_in[15];
    const float* mom_b  = (const float*)d_in[16];
    float* out = (float*)d_out;

    float *p_qi, *p_ki, *p_vi, *p_qp, *p_kp, *p_vp, *p_y, *p_ga;
    cudaGetSymbolAddress((void**)&p_qi, g_qi);
    cudaGetSymbolAddress((void**)&p_ki, g_ki);
    cudaGetSymbolAddress((void**)&p_vi, g_vi);
    cudaGetSymbolAddress((void**)&p_qp, g_qp);
    cudaGetSymbolAddress((void**)&p_kp, g_kp);
    cudaGetSymbolAddress((void**)&p_vp, g_vp);
    cudaGetSymbolAddress((void**)&p_y,  g_y);
    cudaGetSymbolAddress((void**)&p_ga, g_ga);

    cudaMemsetAsync(p_ga, 0, (size_t)BN * 24 * sizeof(float));
    cudaMemsetAsync(p_y,  0, (size_t)BN * DIi * sizeof(float));

    k_rmsnorm<<<BN, 256>>>(x, w_rms);
    k_conv<<<BN, 256>>>(conv_q, conv_k, conv_v);
    dim3 gqkv(DIi/128, BN/128, 3);
    k_gemm3<<<gqkv, 256>>>(p_qi, p_ki, p_vi, wq, wk, wv, p_qp, p_kp, p_vp, DIi, DIMM);
    dim3 ggate(BN/128, 8);
    k_gates2<<<ggate, 256>>>(lr_w, decay_w, mom_w);
    k_mhnorm<<<BN, 256>>>(gamma_q, gamma_k);
    k_scan<<<Bb*Hh*8, 256>>>(lr_b, decay_b, mom_b);
    dim3 gout(DIMM/128, BN/128);
    k_gemm1<<<gout, 256>>>(p_y, wo, out, DIMM, DIi);
}